// round 16
// baseline (speedup 1.0000x reference)
#include <cuda_runtime.h>
#include <cuda_bf16.h>

// Problem shape (fixed by the dataset)
#define BB 32
#define TT 2048
#define DD 512
#define D4 (DD / 4)            // 128 float4 per (b,t) row
#define NCHUNK 256
#define CHUNK (TT / NCHUNK)    // 8 timesteps per block
#define GRID1 (BB * NCHUNK)    // 8192 blocks

// Scratch (device globals, zero-initialized at module load).
// All accumulators/counters are reset by their unique winner each run, so
// every graph replay starts clean. No memset node needed.
__device__ float4 g_colsum[BB * D4];   // per-(b,d4) sum of (p - t), L2-resident (64 KB)
__device__ float  g_wltot;             // global word-loss accumulator
__device__ float  g_sent[BB];          // per-b sentence loss (mean over D)
__device__ int    g_cb[BB];            // per-batch tickets (self-resetting)
__device__ int    g_cg;                // global ticket      (self-resetting)

__device__ __forceinline__ float sl1(float d) {
    float ad = fabsf(d);
    return (ad < 1.0f) ? (0.5f * d * d) : (ad - 0.5f);
}

__device__ __forceinline__ void red_add_v4(float4* addr, float4 v) {
    asm volatile("red.global.add.v4.f32 [%0], {%1, %2, %3, %4};"
                 :: "l"(addr), "f"(v.x), "f"(v.y), "f"(v.z), "f"(v.w) : "memory");
}
__device__ __forceinline__ void red_add_f32(float* addr, float v) {
    asm volatile("red.global.add.f32 [%0], %1;" :: "l"(addr), "f"(v) : "memory");
}
// Release atomic: orders this thread's prior global writes (incl. red) before
// the increment becomes visible — no standalone membar needed.
__device__ __forceinline__ int atom_add_release(int* addr, int v) {
    int old;
    asm volatile("atom.release.gpu.global.add.s32 %0, [%1], %2;"
                 : "=r"(old) : "l"(addr), "r"(v) : "memory");
    return old;
}

// ---------------------------------------------------------------------------
// Single fused kernel. grid = 8192, block = 128, <=64 regs (occ target 8).
// Phase A: stream my 8-row chunk, fold into g_colsum via red.v4, word loss
//          via red.f32.
// Phase B: last block of each batch (release-ticket) folds that batch's
//          sentence loss from L2-hot g_colsum and re-zeroes it.
// Phase C: last batch winner folds 32 sentence values + g_wltot -> out[0].
// No spin-waits anywhere (deadlock-free); unique winners reset all state.
// ---------------------------------------------------------------------------
__global__ void __launch_bounds__(128, 8)
fused(const float4* __restrict__ p,
      const float4* __restrict__ q,
      const int* __restrict__ lens,
      float* __restrict__ out) {
    const int b   = blockIdx.x >> 8;           // / NCHUNK
    const int c   = blockIdx.x & (NCHUNK - 1);
    const int tid = threadIdx.x;

    const int len = __ldg(lens + b);
    const int t0  = c * CHUNK;
    const int t1  = min(t0 + CHUNK, len);

    float wl = 0.f;

    // ---------------- Phase A: stream my chunk ----------------
    if (t1 > t0) {
        float4 sd = make_float4(0.f, 0.f, 0.f, 0.f);
        const float4* __restrict__ pp = p + ((size_t)b * TT + t0) * D4 + tid;
        const float4* __restrict__ pq = q + ((size_t)b * TT + t0) * D4 + tid;
        const int n = t1 - t0;
        if (n == CHUNK) {
            // fast path: 8 rows in two 4-row batches; 8 LDG.128 issued
            // back-to-back before any consumption.
            #pragma unroll
            for (int h = 0; h < 2; ++h) {
                float4 A0 = __ldcs(pp + (size_t)(h * 4 + 0) * D4);
                float4 A1 = __ldcs(pp + (size_t)(h * 4 + 1) * D4);
                float4 A2 = __ldcs(pp + (size_t)(h * 4 + 2) * D4);
                float4 A3 = __ldcs(pp + (size_t)(h * 4 + 3) * D4);
                float4 B0 = __ldcs(pq + (size_t)(h * 4 + 0) * D4);
                float4 B1 = __ldcs(pq + (size_t)(h * 4 + 1) * D4);
                float4 B2 = __ldcs(pq + (size_t)(h * 4 + 2) * D4);
                float4 B3 = __ldcs(pq + (size_t)(h * 4 + 3) * D4);

                float d0x = A0.x - B0.x, d0y = A0.y - B0.y, d0z = A0.z - B0.z, d0w = A0.w - B0.w;
                float d1x = A1.x - B1.x, d1y = A1.y - B1.y, d1z = A1.z - B1.z, d1w = A1.w - B1.w;
                float d2x = A2.x - B2.x, d2y = A2.y - B2.y, d2z = A2.z - B2.z, d2w = A2.w - B2.w;
                float d3x = A3.x - B3.x, d3y = A3.y - B3.y, d3z = A3.z - B3.z, d3w = A3.w - B3.w;

                sd.x += d0x + d1x + d2x + d3x;
                sd.y += d0y + d1y + d2y + d3y;
                sd.z += d0z + d1z + d2z + d3z;
                sd.w += d0w + d1w + d2w + d3w;

                wl += sl1(d0x) + sl1(d0y) + sl1(d0z) + sl1(d0w)
                    + sl1(d1x) + sl1(d1y) + sl1(d1z) + sl1(d1w)
                    + sl1(d2x) + sl1(d2y) + sl1(d2z) + sl1(d2w)
                    + sl1(d3x) + sl1(d3y) + sl1(d3z) + sl1(d3w);
            }
        } else {
            for (int i = 0; i < n; ++i) {
                float4 a  = __ldcs(pp + (size_t)i * D4);
                float4 bt = __ldcs(pq + (size_t)i * D4);
                float dx = a.x - bt.x, dy = a.y - bt.y;
                float dz = a.z - bt.z, dw = a.w - bt.w;
                sd.x += dx; sd.y += dy; sd.z += dz; sd.w += dw;
                wl += sl1(dx) + sl1(dy) + sl1(dz) + sl1(dw);
            }
        }
        red_add_v4(&g_colsum[b * D4 + tid], sd);
    }

    // block-reduce word loss (4 warps), single scalar red per block
    #pragma unroll
    for (int o = 16; o > 0; o >>= 1) wl += __shfl_down_sync(0xffffffffu, wl, o);
    __shared__ float s4[4];
    __shared__ int   flag;
    if ((tid & 31) == 0) s4[tid >> 5] = wl;
    __syncthreads();
    if (tid == 0) {
        red_add_f32(&g_wltot, s4[0] + s4[1] + s4[2] + s4[3]);
        // release-ticket: orders this block's reds before the increment
        int t = atom_add_release(&g_cb[b], 1);
        flag = (t == NCHUNK - 1);
        if (flag) g_cb[b] = 0;                  // unique winner resets
    }
    __syncthreads();
    if (!flag) return;

    // ---------------- Phase B: batch winner folds sentence loss ----------------
    __threadfence();                            // acquire: peers' reds visible
    float4 s = g_colsum[b * D4 + tid];          // L2-hot, 1 float4/thread
    g_colsum[b * D4 + tid] = make_float4(0.f, 0.f, 0.f, 0.f);  // clean for replay

    const float inv_len = 1.0f / (float)len;
    float v = sl1(s.x * inv_len) + sl1(s.y * inv_len)
            + sl1(s.z * inv_len) + sl1(s.w * inv_len);
    #pragma unroll
    for (int o = 16; o > 0; o >>= 1) v += __shfl_down_sync(0xffffffffu, v, o);
    __syncthreads();                            // s4 reuse
    if ((tid & 31) == 0) s4[tid >> 5] = v;
    __syncthreads();

    if (tid == 0) {
        g_sent[b] = (s4[0] + s4[1] + s4[2] + s4[3]) / (float)DD;
        int t = atom_add_release(&g_cg, 1);     // orders g_sent store
        flag = (t == BB - 1);
        if (flag) g_cg = 0;
    }
    __syncthreads();
    if (!flag) return;

    // ---------------- Phase C: global winner writes the output ----------------
    __threadfence();                            // acquire: all g_sent + wl reds visible
    if (tid < 32) {
        float sn = g_sent[tid];
        float ls = (float)__ldg(lens + tid);
        #pragma unroll
        for (int o = 16; o > 0; o >>= 1) {
            sn += __shfl_down_sync(0xffffffffu, sn, o);
            ls += __shfl_down_sync(0xffffffffu, ls, o);
        }
        if (tid == 0) {
            float wt = g_wltot;
            out[0] = wt / (ls * (float)DD) + sn / (float)BB;
            g_wltot = 0.f;                      // reset for next replay
        }
    }
}

extern "C" void kernel_launch(void* const* d_in, const int* in_sizes, int n_in,
                              void* d_out, int out_size) {
    const float4* preds   = (const float4*)d_in[0];
    const float4* targets = (const float4*)d_in[1];
    const int*    lens    = (const int*)d_in[2];
    float*        out     = (float*)d_out;

    fused<<<GRID1, 128>>>(preds, targets, lens, out);
}